// round 2
// baseline (speedup 1.0000x reference)
#include <cuda_runtime.h>

// KAN 3x3 convolution, single channel.
//   spline part: cubic B-spline on uniform grid h=0.4, lo=-1, G=5, order 3.
//   x in [0,1) -> knot interval j in {5,6,7}; active coeffs c = j-3 .. j  (subset of 2..7).
//   Uniform cubic basis (u = local coord in [0,1)):
//     n0=(1-u)^3/6, n1=(3u^3-6u^2+4)/6, n2=(-3u^3+3u^2+3u+1)/6, n3=u^3/6, sum=1.
//   Dense-6 m-vector over slots c=2..7: m[jj+i] = n_i, jj = j-5 in {0,1,2}.
//   Per input pixel: g_p = sum_s m_s*sw[p][s+2] + silu(x)*bw[p], p = a*3+b.
//   Per output: out(h,w) = sum_{a,b} g_{a*3+b}(h+a, w+b).

#define TW 64
#define TH 16
#define IW (TW + 2)         // 66 input cols per tile
#define IH (TH + 2)         // 18 input rows per tile
#define GP (IW + 2)         // padded smem row stride (68)
#define NPIX (IH * IW)      // 1188
#define NTHREADS 256
#define WIDTH 256
#define HO 254
#define WO 254

__global__ void __launch_bounds__(NTHREADS)
kan_conv_kernel(const float* __restrict__ X,
                const float* __restrict__ BWg,
                const float* __restrict__ SWg,
                float* __restrict__ OUT)
{
    __shared__ float gs[9][IH][GP];   // 9 * 18 * 68 * 4 = 44064 B

    const int tid = threadIdx.x;
    const int w0  = blockIdx.x * TW;
    const int h0  = blockIdx.y * TH;
    const float* Xi = X + (size_t)blockIdx.z * (WIDTH * WIDTH);

    // Weights into registers (uniform across threads; broadcast L1 hits).
    float BW[9];
    float SW[9][6];
#pragma unroll
    for (int p = 0; p < 9; ++p) {
        BW[p] = __ldg(BWg + p);
#pragma unroll
        for (int s = 0; s < 6; ++s) SW[p][s] = __ldg(SWg + p * 8 + 2 + s);
    }

    // ---------------- Phase 1: per-input-pixel g values -> smem planes ----
#pragma unroll
    for (int it = 0; it < (NPIX + NTHREADS - 1) / NTHREADS; ++it) {
        int i = tid + it * NTHREADS;
        bool valid = (i < NPIX);
        int ii = valid ? i : 0;
        int r = ii / IW;
        int c = ii - r * IW;
        int gr = min(h0 + r, WIDTH - 1);
        int gc = min(w0 + c, WIDTH - 1);
        float x = __ldg(Xi + gr * WIDTH + gc);

        // interval + local coordinate
        float y  = fmaf(x, 2.5f, 5.5f);       // (x - (-2.2)) / 0.4
        float jf = floorf(y);
        jf = fminf(fmaxf(jf, 5.0f), 7.0f);    // clamp (x in [0,1) anyway)
        float u  = y - jf;
        int  jj  = (int)jf - 5;               // 0..2

        // uniform cubic B-spline basis
        const float c16 = 0.16666666666666666f;
        float omu  = 1.0f - u;
        float u2   = u * u;
        float omu2 = omu * omu;
        float n0 = omu2 * omu * c16;
        float n3 = u2 * u * c16;
        float n1 = fmaf(u2, fmaf(0.5f, u, -1.0f), 0.6666666666666666f);
        float n2 = 1.0f - n0 - n1 - n3;       // partition of unity

        // place 4-window at offset jj in 6 slots (selects ride the ALU pipe)
        bool j0 = (jj == 0), j1 = (jj == 1);
        float m0 = j0 ? n0 : 0.0f;
        float m1 = j0 ? n1 : (j1 ? n0 : 0.0f);
        float m2 = j0 ? n2 : (j1 ? n1 : n0);
        float m3 = j0 ? n3 : (j1 ? n2 : n1);
        float m4 = j1 ? n3 : (j0 ? 0.0f : n2);
        float m5 = (j0 || j1) ? 0.0f : n3;

        // silu(x) = x / (1 + e^{-x})
        float e = __expf(-x);
        float s = x * __fdividef(1.0f, 1.0f + e);

        if (valid) {
#pragma unroll
            for (int p = 0; p < 9; ++p) {
                float g = s * BW[p];
                g = fmaf(m0, SW[p][0], g);
                g = fmaf(m1, SW[p][1], g);
                g = fmaf(m2, SW[p][2], g);
                g = fmaf(m3, SW[p][3], g);
                g = fmaf(m4, SW[p][4], g);
                g = fmaf(m5, SW[p][5], g);
                gs[p][r][c] = g;
            }
        }
    }
    __syncthreads();

    // ---------------- Phase 2: 9-tap gather of g planes -------------------
    const int lw  = tid & (TW - 1);
    const int lh0 = (tid >> 6) << 2;          // {0,4,8,12}
    const int w   = w0 + lw;
    float* Ob = OUT + (size_t)blockIdx.z * (HO * WO) + w;

    if (w < WO) {
#pragma unroll
        for (int d = 0; d < 4; ++d) {
            int lh = lh0 + d;
            int h  = h0 + lh;
            if (h < HO) {
                float acc = 0.0f;
#pragma unroll
                for (int a = 0; a < 3; ++a)
#pragma unroll
                    for (int b = 0; b < 3; ++b)
                        acc += gs[a * 3 + b][lh + a][lw + b];
                Ob[(size_t)h * WO] = acc;
            }
        }
    }
}

extern "C" void kernel_launch(void* const* d_in, const int* in_sizes, int n_in,
                              void* d_out, int out_size)
{
    const float* x  = (const float*)d_in[0];
    const float* bw = (const float*)d_in[1];
    const float* sw = (const float*)d_in[2];
    float* out = (float*)d_out;

    int batch = in_sizes[0] / (WIDTH * WIDTH);   // 32
    dim3 grid((WO + TW - 1) / TW, (HO + TH - 1) / TH, batch);
    kan_conv_kernel<<<grid, NTHREADS>>>(x, bw, sw, out);
}

// round 3
// speedup vs baseline: 1.0015x; 1.0015x over previous
#include <cuda_runtime.h>

// KAN 3x3 convolution, single channel, uniform cubic B-spline (G=5, s=3, h=0.4).
// x in [0,1) -> knot interval j in {5,6,7}; 4 active bases placed in 6 slots (c=2..7).
// Phase 1: per input pixel compute g_p = silu(x)*bw[p] + sum_s m_s*sw[p][s+2] for the
//          9 taps p=(a,b); store into 9 smem planes SHIFTED by -b so phase 2 reads all
//          planes at one column. Packed f32x2 FMAs over plane pairs.
// Phase 2: out(h,w..w+3) = sum over 9 planes of one aligned float4 each.

#define TW 64
#define TH 16
#define IW (TW + 2)          // 66
#define IH (TH + 2)          // 18
#define GPAD 72              // padded row stride (floats), 16B-aligned vec reads
#define PS (IH * GPAD)       // plane stride = 1296 floats
#define NPIX (IH * IW)       // 1188
#define NTHREADS 256
#define NITER ((NPIX + NTHREADS - 1) / NTHREADS)   // 5
#define WIDTH 256
#define HO 254
#define WO 254

typedef unsigned long long ull;

#define PACK2(d, lo, hi)   asm("mov.b64 %0, {%1, %2};" : "=l"(d) : "f"(lo), "f"(hi))
#define UNPACK2(lo, hi, s) asm("mov.b64 {%0, %1}, %2;" : "=f"(lo), "=f"(hi) : "l"(s))
#define FMA2(d, a, b, c)   asm("fma.rn.f32x2 %0, %1, %2, %3;" : "=l"(d) : "l"(a), "l"(b), "l"(c))
#define MUL2(d, a, b)      asm("mul.rn.f32x2 %0, %1, %2;" : "=l"(d) : "l"(a), "l"(b))
#define ADD2(d, a, b)      asm("add.rn.f32x2 %0, %1, %2;" : "=l"(d) : "l"(a), "l"(b))

__global__ void __launch_bounds__(NTHREADS)
kan_conv_kernel(const float* __restrict__ X,
                const float* __restrict__ BWg,
                const float* __restrict__ SWg,
                float* __restrict__ OUT)
{
    __shared__ __align__(16) float gs[9 * PS];   // 9*1296*4 = 46656 B

    const int tid = threadIdx.x;
    const int w0  = blockIdx.x * TW;
    const int h0  = blockIdx.y * TH;
    const float* Xi = X + (size_t)blockIdx.z * (WIDTH * WIDTH);

    // ---- weights -> registers; pack plane pairs (0,1)(2,3)(4,5)(6,7); plane 8 scalar
    float BW[9], SW[9][6];
#pragma unroll
    for (int p = 0; p < 9; ++p) {
        BW[p] = __ldg(BWg + p);
#pragma unroll
        for (int s = 0; s < 6; ++s) SW[p][s] = __ldg(SWg + p * 8 + 2 + s);
    }
    ull B2[4], W2[4][6];
#pragma unroll
    for (int q = 0; q < 4; ++q) {
        PACK2(B2[q], BW[2 * q], BW[2 * q + 1]);
#pragma unroll
        for (int s = 0; s < 6; ++s) PACK2(W2[q][s], SW[2 * q][s], SW[2 * q + 1][s]);
    }

    // ---------------- Phase 1 ----------------
    // front-batched global loads (MLP = NITER)
    float xv[NITER];
    int   rr[NITER], cc[NITER];
#pragma unroll
    for (int it = 0; it < NITER; ++it) {
        int i  = tid + it * NTHREADS;
        int ii = (i < NPIX) ? i : 0;
        int r  = ii / IW;
        int c  = ii - r * IW;
        rr[it] = r; cc[it] = c;
        int gr = min(h0 + r, WIDTH - 1);
        int gc = min(w0 + c, WIDTH - 1);
        xv[it] = __ldg(Xi + gr * WIDTH + gc);
    }

#pragma unroll
    for (int it = 0; it < NITER; ++it) {
        float x = xv[it];

        float y  = fmaf(x, 2.5f, 5.5f);          // (x + 2.2) / 0.4
        float jf = floorf(y);                    // in {5,6,7} for x in [0,1)
        jf = fminf(jf, 7.0f);
        float u  = y - jf;

        const float c16 = 0.16666666666666666f;
        float omu  = 1.0f - u;
        float u2   = u * u;
        float n0 = omu * omu * omu * c16;
        float n3 = u2 * u * c16;
        float n1 = fmaf(u2, fmaf(0.5f, u, -1.0f), 0.6666666666666666f);
        float n2 = 1.0f - n0 - n1 - n3;          // partition of unity

        bool j0 = (jf == 5.0f), j1 = (jf == 6.0f);
        float m0 = j0 ? n0 : 0.0f;
        float m1 = j0 ? n1 : (j1 ? n0 : 0.0f);
        float m2 = j0 ? n2 : (j1 ? n1 : n0);
        float m3 = j0 ? n3 : (j1 ? n2 : n1);
        float m4 = j0 ? 0.0f : (j1 ? n3 : n2);
        float m5 = (j0 || j1) ? 0.0f : n3;

        float e = __expf(-x);
        float s = x * __fdividef(1.0f, 1.0f + e);

        ull M[6], Sp;
        PACK2(M[0], m0, m0); PACK2(M[1], m1, m1); PACK2(M[2], m2, m2);
        PACK2(M[3], m3, m3); PACK2(M[4], m4, m4); PACK2(M[5], m5, m5);
        PACK2(Sp, s, s);

        ull G[4];
#pragma unroll
        for (int q = 0; q < 4; ++q) {
            MUL2(G[q], Sp, B2[q]);
#pragma unroll
            for (int i = 0; i < 6; ++i) FMA2(G[q], M[i], W2[q][i], G[q]);
        }
        float g8 = s * BW[8];
        g8 = fmaf(m0, SW[8][0], g8); g8 = fmaf(m1, SW[8][1], g8);
        g8 = fmaf(m2, SW[8][2], g8); g8 = fmaf(m3, SW[8][3], g8);
        g8 = fmaf(m4, SW[8][4], g8); g8 = fmaf(m5, SW[8][5], g8);

        if (tid + it * NTHREADS < NPIX) {
            // plane p=(a,b): write col c - b + 4   (b = p % 3)
            float* base = gs + rr[it] * GPAD + cc[it] + 4;
            float glo, ghi;
            UNPACK2(glo, ghi, G[0]); base[0 * PS - 0] = glo; base[1 * PS - 1] = ghi;
            UNPACK2(glo, ghi, G[1]); base[2 * PS - 2] = glo; base[3 * PS - 0] = ghi;
            UNPACK2(glo, ghi, G[2]); base[4 * PS - 1] = glo; base[5 * PS - 2] = ghi;
            UNPACK2(glo, ghi, G[3]); base[6 * PS - 0] = glo; base[7 * PS - 1] = ghi;
            base[8 * PS - 2] = g8;
        }
    }
    __syncthreads();

    // ---------------- Phase 2: 4 outputs/thread, 9 aligned 16B smem loads ----
    const int lw4 = (tid & 15) * 4;
    const int lh  = tid >> 4;
    const int h   = h0 + lh;

    if (h < HO) {
        const char* rbase = (const char*)(gs + lh * GPAD + lw4 + 4);
        ulonglong2 v0 = *(const ulonglong2*)(rbase);
        ull alo = v0.x, ahi = v0.y;
#pragma unroll
        for (int a = 0; a < 3; ++a)
#pragma unroll
            for (int b = 0; b < 3; ++b) {
                if (a == 0 && b == 0) continue;
                ulonglong2 v = *(const ulonglong2*)(rbase +
                        ((a * 3 + b) * PS + a * GPAD) * sizeof(float));
                ADD2(alo, alo, v.x);
                ADD2(ahi, ahi, v.y);
            }

        const int w = w0 + lw4;
        float* op = OUT + (size_t)blockIdx.z * (HO * WO) + (size_t)h * WO + w;
        if (w + 3 < WO) {                     // 8B-aligned pair stores
            *(ull*)(op)     = alo;
            *(ull*)(op + 2) = ahi;
        } else {
            float f0, f1, f2, f3;
            UNPACK2(f0, f1, alo);
            UNPACK2(f2, f3, ahi);
            if (w     < WO) op[0] = f0;
            if (w + 1 < WO) op[1] = f1;
            if (w + 2 < WO) op[2] = f2;
            if (w + 3 < WO) op[3] = f3;
        }
    }
}

extern "C" void kernel_launch(void* const* d_in, const int* in_sizes, int n_in,
                              void* d_out, int out_size)
{
    const float* x  = (const float*)d_in[0];
    const float* bw = (const float*)d_in[1];
    const float* sw = (const float*)d_in[2];
    float* out = (float*)d_out;

    int batch = in_sizes[0] / (WIDTH * WIDTH);   // 32
    dim3 grid((WO + TW - 1) / TW, (HO + TH - 1) / TH, batch);
    kan_conv_kernel<<<grid, NTHREADS>>>(x, bw, sw, out);
}

// round 4
// speedup vs baseline: 1.1083x; 1.1066x over previous
#include <cuda_runtime.h>

// KAN 3x3 convolution, single channel, uniform cubic B-spline (G=5, s=3, h=0.4).
// x in [0,1) -> knot interval j in {5,6,7}; 4 active bases placed in 6 slots (c=2..7).
// Phase 1: per input pixel g_p = silu(x)*bw[p] + sum_s m_s*sw[p][s+2], 9 taps p=(a,b);
//          weights come from __constant__ (uniform-register path) so thread GPR count
//          stays low. Planes stored SHIFTED by -b so phase 2 reads one column.
// Phase 2: out(h, w..w+3) = sum over 9 planes of one aligned float4 each (LDS.128 + f32x2 adds).

#define TW 64
#define TH 16
#define IW (TW + 2)          // 66
#define IH (TH + 2)          // 18
#define GPAD 72              // padded row stride (floats), keeps 16B alignment
#define PS (IH * GPAD)       // plane stride = 1296 floats
#define NPIX (IH * IW)       // 1188
#define NTHREADS 256
#define NITER ((NPIX + NTHREADS - 1) / NTHREADS)   // 5
#define WIDTH 256
#define HO 254
#define WO 254

typedef unsigned long long ull;

#define UNPACK2(lo, hi, s) asm("mov.b64 {%0, %1}, %2;" : "=f"(lo), "=f"(hi) : "l"(s))
#define ADD2(d, a, b)      asm("add.rn.f32x2 %0, %1, %2;" : "=l"(d) : "l"(a), "l"(b))

__constant__ float cBW[9];     // base weights, flattened 3x3
__constant__ float cSW[72];    // spline weights, [9][8]

__global__ void __launch_bounds__(NTHREADS, 4)
kan_conv_kernel(const float* __restrict__ X,
                float* __restrict__ OUT)
{
    __shared__ __align__(16) float gs[9 * PS];   // 46656 B

    const int tid = threadIdx.x;
    const int w0  = blockIdx.x * TW;
    const int h0  = blockIdx.y * TH;
    const float* Xi = X + (size_t)blockIdx.z * (WIDTH * WIDTH);

    // ---------------- Phase 1 ----------------
    // front-batched global loads (MLP = NITER)
    float xv[NITER];
#pragma unroll
    for (int it = 0; it < NITER; ++it) {
        int i  = tid + it * NTHREADS;
        int ii = (i < NPIX) ? i : 0;
        int r  = ii / IW;
        int c  = ii - r * IW;
        int gr = min(h0 + r, WIDTH - 1);
        int gc = min(w0 + c, WIDTH - 1);
        xv[it] = __ldg(Xi + gr * WIDTH + gc);
    }

#pragma unroll
    for (int it = 0; it < NITER; ++it) {
        int i  = tid + it * NTHREADS;
        int ii = (i < NPIX) ? i : 0;
        int r  = ii / IW;
        int c  = ii - r * IW;
        float x = xv[it];

        float y  = fmaf(x, 2.5f, 5.5f);          // (x + 2.2) / 0.4
        float jf = floorf(y);                    // in {5,6,7} for x in [0,1)
        jf = fminf(jf, 7.0f);
        float u  = y - jf;

        const float c16 = 0.16666666666666666f;
        float omu = 1.0f - u;
        float u2  = u * u;
        float n0 = omu * omu * omu * c16;
        float n3 = u2 * u * c16;
        float n1 = fmaf(u2, fmaf(0.5f, u, -1.0f), 0.6666666666666666f);
        float n2 = 1.0f - n0 - n1 - n3;          // partition of unity

        bool j0 = (jf == 5.0f), j1 = (jf == 6.0f);
        float m0 = j0 ? n0 : 0.0f;
        float m1 = j0 ? n1 : (j1 ? n0 : 0.0f);
        float m2 = j0 ? n2 : (j1 ? n1 : n0);
        float m3 = j0 ? n3 : (j1 ? n2 : n1);
        float m4 = j0 ? 0.0f : (j1 ? n3 : n2);
        float m5 = (j0 || j1) ? 0.0f : n3;

        // silu(x) = x / (1 + e^{-x})
        float e = __expf(-x);
        float s = x * __fdividef(1.0f, 1.0f + e);

        if (i < NPIX) {
            float* base = gs + r * GPAD + c + 4;   // plane p=(a,b) writes col c - b + 4
#pragma unroll
            for (int p = 0; p < 9; ++p) {
                float g = s * cBW[p];
                g = fmaf(m0, cSW[p * 8 + 2], g);
                g = fmaf(m1, cSW[p * 8 + 3], g);
                g = fmaf(m2, cSW[p * 8 + 4], g);
                g = fmaf(m3, cSW[p * 8 + 5], g);
                g = fmaf(m4, cSW[p * 8 + 6], g);
                g = fmaf(m5, cSW[p * 8 + 7], g);
                base[p * PS - (p % 3)] = g;
            }
        }
    }
    __syncthreads();

    // ---------------- Phase 2: 4 outputs/thread, 9 aligned 16B smem loads ----
    const int lw4 = (tid & 15) * 4;
    const int lh  = tid >> 4;
    const int h   = h0 + lh;

    if (h < HO) {
        const char* rbase = (const char*)(gs + lh * GPAD + lw4 + 4);
        ulonglong2 v0 = *(const ulonglong2*)(rbase);
        ull alo = v0.x, ahi = v0.y;
#pragma unroll
        for (int a = 0; a < 3; ++a)
#pragma unroll
            for (int b = 0; b < 3; ++b) {
                if (a == 0 && b == 0) continue;
                ulonglong2 v = *(const ulonglong2*)(rbase +
                        ((a * 3 + b) * PS + a * GPAD) * sizeof(float));
                ADD2(alo, alo, v.x);
                ADD2(ahi, ahi, v.y);
            }

        const int w = w0 + lw4;
        float* op = OUT + (size_t)blockIdx.z * (HO * WO) + (size_t)h * WO + w;
        if (w + 3 < WO) {
            *(ull*)(op)     = alo;
            *(ull*)(op + 2) = ahi;
        } else {
            float f0, f1, f2, f3;
            UNPACK2(f0, f1, alo);
            UNPACK2(f2, f3, ahi);
            if (w     < WO) op[0] = f0;
            if (w + 1 < WO) op[1] = f1;
            if (w + 2 < WO) op[2] = f2;
            if (w + 3 < WO) op[3] = f3;
        }
    }
}

extern "C" void kernel_launch(void* const* d_in, const int* in_sizes, int n_in,
                              void* d_out, int out_size)
{
    const float* x  = (const float*)d_in[0];
    float* out = (float*)d_out;

    // Stage block-uniform weights into __constant__ (device-to-device async copy:
    // allowed and graph-capturable as memcpy nodes).
    cudaMemcpyToSymbolAsync(cBW, d_in[1], 9 * sizeof(float), 0,
                            cudaMemcpyDeviceToDevice, 0);
    cudaMemcpyToSymbolAsync(cSW, d_in[2], 72 * sizeof(float), 0,
                            cudaMemcpyDeviceToDevice, 0);

    int batch = in_sizes[0] / (WIDTH * WIDTH);   // 32
    dim3 grid((WO + TW - 1) / TW, (HO + TH - 1) / TH, batch);
    kan_conv_kernel<<<grid, NTHREADS>>>(x, out);
}

// round 8
// speedup vs baseline: 1.2405x; 1.1193x over previous
#include <cuda_runtime.h>

// KAN 3x3 convolution, single channel, uniform cubic B-spline (G=5, s=3, h=0.4).
// x in [0,1) -> knot interval j in {5,6,7}; 4 active bases placed in 6 slots (c=2..7).
// Phase 1: per input pixel g_p = silu(x)*bw[p] + sum_s m_s*sw[p][s+2], 9 taps p=(a,b);
//          spline weights in __constant__ (uniform-register path), base weights via
//          __ldg (9 regs). Planes stored SHIFTED by -b so phase 2 reads one column.
// Phase 2: out(h, w..w+3) = sum over 9 planes of one aligned float4 (LDS.128 + f32x2 adds).

#define TW 64
#define TH 16
#define IW (TW + 2)          // 66
#define IH (TH + 2)          // 18
#define GPAD 68              // padded row stride (floats); 272B rows keep 16B alignment
#define PS (IH * GPAD)       // plane stride = 1224 floats
#define NPIX (IH * IW)       // 1188
#define NTHREADS 256
#define NITER ((NPIX + NTHREADS - 1) / NTHREADS)   // 5
#define WIDTH 256
#define HO 254
#define WO 254

typedef unsigned long long ull;

#define UNPACK2(lo, hi, s) asm("mov.b64 {%0, %1}, %2;" : "=f"(lo), "=f"(hi) : "l"(s))
#define ADD2(d, a, b)      asm("add.rn.f32x2 %0, %1, %2;" : "=l"(d) : "l"(a), "l"(b))

__constant__ float cSW[72];    // spline weights, [9][8]

__global__ void __launch_bounds__(NTHREADS, 5)
kan_conv_kernel(const float* __restrict__ X,
                const float* __restrict__ BWg,
                float* __restrict__ OUT)
{
    // +8 floats: shifted halo writes (col' up to 69 on the last plane/row) stay in-bounds.
    __shared__ __align__(16) float gs[9 * PS + 8];   // 44096 B

    const int tid = threadIdx.x;
    const int w0  = blockIdx.x * TW;
    const int h0  = blockIdx.y * TH;
    const float* Xi = X + (size_t)blockIdx.z * (WIDTH * WIDTH);

    // base weights -> 9 regs (hoisted LDG, block-uniform broadcast hits)
    float BW[9];
#pragma unroll
    for (int p = 0; p < 9; ++p) BW[p] = __ldg(BWg + p);

    // ---------------- Phase 1 ----------------
    // front-batched global loads (MLP = NITER) + precomputed smem base offsets
    float xv[NITER];
    int   sb[NITER];
#pragma unroll
    for (int it = 0; it < NITER; ++it) {
        int i  = tid + it * NTHREADS;
        int ii = (i < NPIX) ? i : 0;
        int r  = ii / IW;
        int c  = ii - r * IW;
        sb[it] = r * GPAD + c + 4;               // plane p writes sb - (p%3)
        int gr = min(h0 + r, WIDTH - 1);
        int gc = min(w0 + c, WIDTH - 1);
        xv[it] = __ldg(Xi + gr * WIDTH + gc);
    }

#pragma unroll
    for (int it = 0; it < NITER; ++it) {
        float x = xv[it];

        float y  = fmaf(x, 2.5f, 5.5f);          // (x + 2.2) / 0.4  -> [5.5, 8.0)
        float jf = floorf(y);                    // in {5,6,7}
        float u  = y - jf;

        const float c16 = 0.16666666666666666f;
        float omu = 1.0f - u;
        float u2  = u * u;
        float n0 = omu * omu * omu * c16;
        float n3 = u2 * u * c16;
        float n1 = fmaf(u2, fmaf(0.5f, u, -1.0f), 0.6666666666666666f);
        float n2 = 1.0f - n0 - n1 - n3;          // partition of unity

        bool j0 = (jf == 5.0f), j1 = (jf == 6.0f);
        float m0 = j0 ? n0 : 0.0f;
        float m1 = j0 ? n1 : (j1 ? n0 : 0.0f);
        float m2 = j0 ? n2 : (j1 ? n1 : n0);
        float m3 = j0 ? n3 : (j1 ? n2 : n1);
        float m4 = j0 ? 0.0f : (j1 ? n3 : n2);
        float m5 = (j0 || j1) ? 0.0f : n3;

        // silu(x) = x / (1 + e^{-x})
        float e = __expf(-x);
        float s = x * __fdividef(1.0f, 1.0f + e);

        if (tid + it * NTHREADS < NPIX) {
            float* base = gs + sb[it];
#pragma unroll
            for (int p = 0; p < 9; ++p) {
                float g = s * BW[p];
                g = fmaf(m0, cSW[p * 8 + 2], g);
                g = fmaf(m1, cSW[p * 8 + 3], g);
                g = fmaf(m2, cSW[p * 8 + 4], g);
                g = fmaf(m3, cSW[p * 8 + 5], g);
                g = fmaf(m4, cSW[p * 8 + 6], g);
                g = fmaf(m5, cSW[p * 8 + 7], g);
                base[p * PS - (p % 3)] = g;
            }
        }
    }
    __syncthreads();

    // ---------------- Phase 2: 4 outputs/thread, 9 aligned 16B smem loads ----
    const int lw4 = (tid & 15) * 4;
    const int lh  = tid >> 4;
    const int h   = h0 + lh;

    if (h < HO) {
        const char* rbase = (const char*)(gs + lh * GPAD + lw4 + 4);
        ulonglong2 v0 = *(const ulonglong2*)(rbase);
        ull alo = v0.x, ahi = v0.y;
#pragma unroll
        for (int a = 0; a < 3; ++a)
#pragma unroll
            for (int b = 0; b < 3; ++b) {
                if (a == 0 && b == 0) continue;
                ulonglong2 v = *(const ulonglong2*)(rbase +
                        ((a * 3 + b) * PS + a * GPAD) * sizeof(float));
                ADD2(alo, alo, v.x);
                ADD2(ahi, ahi, v.y);
            }

        const int w = w0 + lw4;
        float* op = OUT + (size_t)blockIdx.z * (HO * WO) + (size_t)h * WO + w;
        if (w + 3 < WO) {
            *(ull*)(op)     = alo;
            *(ull*)(op + 2) = ahi;
        } else {
            float f0, f1, f2, f3;
            UNPACK2(f0, f1, alo);
            UNPACK2(f2, f3, ahi);
            if (w     < WO) op[0] = f0;
            if (w + 1 < WO) op[1] = f1;
            if (w + 2 < WO) op[2] = f2;
            if (w + 3 < WO) op[3] = f3;
        }
    }
}

extern "C" void kernel_launch(void* const* d_in, const int* in_sizes, int n_in,
                              void* d_out, int out_size)
{
    const float* x  = (const float*)d_in[0];
    const float* bw = (const float*)d_in[1];
    float* out = (float*)d_out;

    // Stage spline weights into __constant__ (one D2D async copy, graph-capturable).
    cudaMemcpyToSymbolAsync(cSW, d_in[2], 72 * sizeof(float), 0,
                            cudaMemcpyDeviceToDevice, 0);

    int batch = in_sizes[0] / (WIDTH * WIDTH);   // 32
    dim3 grid((WO + TW - 1) / TW, (HO + TH - 1) / TH, batch);
    kan_conv_kernel<<<grid, NTHREADS>>>(x, bw, out);
}